// round 12
// baseline (speedup 1.0000x reference)
#include <cuda_runtime.h>
#include <cstdint>

#define NPTS     32768
#define KCODES   1024
#define DDIM     256
#define HWSZ     1024
#define DHW      (DDIM*HWSZ)
#define HALF_OUT 8388608
#define CMAXC    64
#define PPC      111          // points per pass1 CTA (296 x 111 >= 32768)
#define GRID1    296          // 2 CTAs/SM -> exactly one wave

typedef unsigned int u32;
typedef unsigned short u16;
typedef unsigned long long u64;

// Scratch (static __device__ — no allocations)
__device__ u32    g_c8T[KCODES * 64];   // [8 tile][64 word][128 code] packed int8
__device__ float4 g_cs4[KCODES];        // (cc exact-chain, sc=max|c|, rc=||Δc||, 0)
__device__ float  g_xx[NPTS];
__device__ float  g_mar[NPTS];
__device__ float  g_minq[NPTS];
__device__ u16    g_cand[NPTS * CMAXC];
__device__ float  g_cdda[NPTS * CMAXC];
__device__ u32    g_ccnt[NPTS];

__device__ __forceinline__ u32 smem_u32(const void* p) {
    return (u32)__cvta_generic_to_shared(p);
}
__device__ __forceinline__ void cp_async16(u32 dst, const void* src) {
    asm volatile("cp.async.cg.shared.global [%0], [%1], 16;" :: "r"(dst), "l"(src));
}
__device__ __forceinline__ void cp_commit() { asm volatile("cp.async.commit_group;"); }
__device__ __forceinline__ void cp_wait0()  { asm volatile("cp.async.wait_group 0;" ::: "memory"); }

// dp4a micro-tile: 8 points x 4 codes on packed operands
__device__ __forceinline__ void dp32(int* m, uint4 A0, uint4 A1, uint4 B) {
    int a[8] = {(int)A0.x, (int)A0.y, (int)A0.z, (int)A0.w,
                (int)A1.x, (int)A1.y, (int)A1.z, (int)A1.w};
    int bb[4] = {(int)B.x, (int)B.y, (int)B.z, (int)B.w};
    #pragma unroll
    for (int i = 0; i < 8; ++i)
        #pragma unroll
        for (int j = 0; j < 4; ++j)
            m[i * 4 + j] = __dp4a(a[i], bb[j], m[i * 4 + j]);
}

// ncu capture slot is #4: code_prep(1), nop_a(2), pass1(3), exact_gather(4).
__global__ void nop_a() {}

// ---------------------------------------------------------------------------
// code_prep: one WARP per code (unchanged, 6.2us).
// ---------------------------------------------------------------------------
__global__ void code_prep(const float* __restrict__ cb) {
    const int tid = threadIdx.x, lane = tid & 31, wid = tid >> 5;
    const int k = blockIdx.x * 8 + wid;
    const float* row = cb + (size_t)k * DDIM;

    float4 va = *(const float4*)(row + lane * 8);
    float4 vb = *(const float4*)(row + lane * 8 + 4);
    float mx = fmaxf(fmaxf(fmaxf(fabsf(va.x), fabsf(va.y)), fmaxf(fabsf(va.z), fabsf(va.w))),
                     fmaxf(fmaxf(fabsf(vb.x), fabsf(vb.y)), fmaxf(fabsf(vb.z), fabsf(vb.w))));
    #pragma unroll
    for (int o = 16; o; o >>= 1) mx = fmaxf(mx, __shfl_xor_sync(0xFFFFFFFFu, mx, o));

    float mxx = fmaxf(mx, 1e-30f);
    float s127 = 127.0f / mxx;
    float cinv = mxx / 127.0f;

    float rsum = 0.0f;
    u32 base = (u32)(k >> 7) * 8192u + (u32)(k & 127);
    float vv[8] = {va.x, va.y, va.z, va.w, vb.x, vb.y, vb.z, vb.w};
    #pragma unroll
    for (int h = 0; h < 2; ++h) {
        u32 pk = 0;
        #pragma unroll
        for (int e = 0; e < 4; ++e) {
            float ve = vv[h * 4 + e];
            int q = __float2int_rn(ve * s127);
            q = max(-127, min(127, q));
            float diff = fmaf(-(float)q, cinv, ve);
            rsum += diff * diff;
            pk |= ((u32)(q & 0xFF)) << (8 * e);
        }
        g_c8T[base + (u32)(lane * 2 + h) * 128u] = pk;
    }
    #pragma unroll
    for (int o = 16; o; o >>= 1) rsum += __shfl_xor_sync(0xFFFFFFFFu, rsum, o);

    if (lane == 0) {
        float s = 0.0f;
        for (int d0 = 0; d0 < DDIM; d0 += 16) {
            float4 w0 = *(const float4*)(row + d0);
            float4 w1 = *(const float4*)(row + d0 + 4);
            float4 w2 = *(const float4*)(row + d0 + 8);
            float4 w3 = *(const float4*)(row + d0 + 12);
            float v[16] = {w0.x, w0.y, w0.z, w0.w, w1.x, w1.y, w1.z, w1.w,
                           w2.x, w2.y, w2.z, w2.w, w3.x, w3.y, w3.z, w3.w};
            #pragma unroll
            for (int e = 0; e < 16; ++e)
                s = __fadd_rn(s, __fmul_rn(v[e], v[e]));
        }
        g_cs4[k] = make_float4(s, mx, sqrtf(rsum) * 1.02f + 1e-7f, 0.0f);
    }
}

// ---------------------------------------------------------------------------
// Pass 1: 512 threads, 8pts x 4codes, 2 CTAs/SM. Software-pipelined mainloop
// (prefetch w+1 operands into registers, dp4a on w). cc/sc cached in smem.
// ---------------------------------------------------------------------------
__global__ void __launch_bounds__(512, 2)
pass1_kernel(const float* __restrict__ z) {
    extern __shared__ u32 sdyn[];   // As[8192] | Bs0[8192] | Bs1[8192] | sCS[2048]
    u32* As = sdyn;
    u32* Bsb[2] = { sdyn + 8192, sdyn + 16384 };
    float2* sCS = (float2*)(sdyn + 24576);      // (cc, sc) per code, 8KB
    __shared__ float sMar[128], sXX[128], sSX[128], sRX[128];
    __shared__ float sred[2][16];

    const int tid = threadIdx.x;
    const int tx = tid & 31;          // lane -> 4 codes at tx*4
    const int ty = tid >> 5;          // warp -> 8 points at ty*8
    const int p0 = blockIdx.x * PPC;
    const int npts = min(PPC, NPTS - p0);

    // Prefetch B tile 0 (overlaps entire prologue)
    {
        u32 db = smem_u32(Bsb[0]);
        #pragma unroll
        for (int r = 0; r < 4; ++r)
            cp_async16(db + (u32)(r * 512 + tid) * 16u, g_c8T + (r * 512 + tid) * 4);
        cp_commit();
    }

    // Preload (cc, sc) into smem + block maxes (cc, rc)
    {
        float mcc = 0.0f, mrc = 0.0f;
        #pragma unroll
        for (int l = 0; l < 2; ++l) {
            int k = tid + l * 512;
            float4 cs = g_cs4[k];
            sCS[k] = make_float2(cs.x, cs.y);
            mcc = fmaxf(mcc, cs.x);
            mrc = fmaxf(mrc, cs.z);
        }
        #pragma unroll
        for (int o = 16; o; o >>= 1) {
            mcc = fmaxf(mcc, __shfl_xor_sync(0xFFFFFFFFu, mcc, o));
            mrc = fmaxf(mrc, __shfl_xor_sync(0xFFFFFFFFu, mrc, o));
        }
        if (tx == 0) { sred[0][ty] = mcc; sred[1][ty] = mrc; }
    }

    // x-prep: threads 0-127 pinned xx chains; 128-255 pack + residual.
    if (tid < 128) {
        const int p = tid, n = p0 + p;
        if (p < npts) {
            const int bb = n >> 10, hw = n & 1023;
            const float* bp = z + (size_t)bb * DHW + hw;
            g_ccnt[n] = 0;
            float s = 0.0f;
            for (int d0 = 0; d0 < DDIM; d0 += 16) {
                float v[16];
                #pragma unroll
                for (int e = 0; e < 16; ++e) v[e] = bp[(size_t)(d0 + e) * HWSZ];
                #pragma unroll
                for (int e = 0; e < 16; ++e)
                    s = __fadd_rn(s, __fmul_rn(v[e], v[e]));
            }
            g_xx[n] = s;
            sXX[p] = s;
        } else {
            sXX[p] = 3.0e38f;
        }
    } else if (tid < 256) {
        const int p = tid - 128, n = p0 + p;
        if (p < npts) {
            const int bb = n >> 10, hw = n & 1023;
            const float* bp = z + (size_t)bb * DHW + hw;
            float mx = 0.0f;
            for (int d0 = 0; d0 < DDIM; d0 += 16) {
                float v[16];
                #pragma unroll
                for (int e = 0; e < 16; ++e) v[e] = bp[(size_t)(d0 + e) * HWSZ];
                #pragma unroll
                for (int e = 0; e < 16; ++e) mx = fmaxf(mx, fabsf(v[e]));
            }
            float mxx = fmaxf(mx, 1e-30f);
            float s127 = 127.0f / mxx;
            float xinv = mxx / 127.0f;
            float rsum = 0.0f;
            #pragma unroll 4
            for (int w = 0; w < 64; ++w) {
                u32 pk = 0;
                #pragma unroll
                for (int e = 0; e < 4; ++e) {
                    float xe = bp[(size_t)(w * 4 + e) * HWSZ];   // L2 hit
                    int q = __float2int_rn(xe * s127);
                    q = max(-127, min(127, q));
                    float diff = fmaf(-(float)q, xinv, xe);
                    rsum += diff * diff;
                    pk |= ((u32)(q & 0xFF)) << (8 * e);
                }
                As[w * 128 + p] = pk;
            }
            sSX[p] = mx * (1.0f / 16129.0f);
            sRX[p] = sqrtf(rsum) * 1.02f + 1e-7f;
        } else {
            #pragma unroll 8
            for (int w = 0; w < 64; ++w) As[w * 128 + p] = 0u;
            sSX[p] = 0.0f;
            sRX[p] = 0.0f;
        }
    }
    __syncthreads();

    float MCC = 0.0f, MRC = 0.0f;
    #pragma unroll
    for (int i = 0; i < 16; ++i) {
        MCC = fmaxf(MCC, sred[0][i]);
        MRC = fmaxf(MRC, sred[1][i]);
    }
    const float Smax = sqrtf(MCC);

    if (tid < 128) {
        const int p = tid;
        if (p < npts) {
            float rx = sRX[p], s = sXX[p];
            float errdot = rx * Smax + (sqrtf(s) + rx) * MRC;
            float marg = 2.5f * errdot + 2e-4f;
            sMar[p] = marg;
            g_mar[p0 + p] = marg;
        } else {
            sMar[p] = 0.0f;
        }
    }
    cp_wait0();
    __syncthreads();

    float gmin8[8];
    #pragma unroll
    for (int i = 0; i < 8; ++i) gmin8[i] = 3.0e38f;

    for (int t = 0; t < 8; ++t) {
        if (t < 7) {
            u32 db = smem_u32(Bsb[(t + 1) & 1]);
            const u32* src = g_c8T + (t + 1) * 8192;
            #pragma unroll
            for (int r = 0; r < 4; ++r)
                cp_async16(db + (u32)(r * 512 + tid) * 16u, src + (r * 512 + tid) * 4);
            cp_commit();
        }
        const uint4* Bt4 = (const uint4*)Bsb[t & 1];
        const uint4* At4 = (const uint4*)As;

        int m[32];
        #pragma unroll
        for (int i = 0; i < 32; ++i) m[i] = 0;

        // Software-pipelined mainloop: operands for w+1 in flight during w.
        {
            uint4 a0c = At4[ty * 2], a1c = At4[ty * 2 + 1], bc = Bt4[tx];
            #pragma unroll 2
            for (int w = 0; w < 64; w += 2) {
                uint4 a0n = At4[(w + 1) * 32 + ty * 2];
                uint4 a1n = At4[(w + 1) * 32 + ty * 2 + 1];
                uint4 bn  = Bt4[(w + 1) * 32 + tx];
                dp32(m, a0c, a1c, bc);
                if (w + 2 < 64) {
                    a0c = At4[(w + 2) * 32 + ty * 2];
                    a1c = At4[(w + 2) * 32 + ty * 2 + 1];
                    bc  = Bt4[(w + 2) * 32 + tx];
                }
                dp32(m, a0n, a1n, bn);
            }
        }

        // Epilogue: distances (cc/sc from smem) + full-warp shuffle min
        {
            float xx8[8], sx8[8], lmin8[8];
            #pragma unroll
            for (int i = 0; i < 8; ++i) {
                xx8[i] = sXX[ty * 8 + i];
                sx8[i] = sSX[ty * 8 + i];
                lmin8[i] = 3.0e38f;
            }
            #pragma unroll
            for (int j = 0; j < 4; ++j) {
                float2 cj = sCS[t * 128 + tx * 4 + j];
                #pragma unroll
                for (int i = 0; i < 8; ++i) {
                    float dd = fmaf(-2.0f * sx8[i] * cj.y,
                                    (float)m[i * 4 + j], xx8[i] + cj.x);
                    m[i * 4 + j] = __float_as_int(dd);
                    lmin8[i] = fminf(lmin8[i], dd);
                }
            }
            #pragma unroll
            for (int i = 0; i < 8; ++i) {
                float v = lmin8[i];
                #pragma unroll
                for (int o = 1; o < 32; o <<= 1)
                    v = fminf(v, __shfl_xor_sync(0xFFFFFFFFu, v, o));
                gmin8[i] = fminf(gmin8[i], v);
            }
            // Collect superset (guard pad slots)
            #pragma unroll
            for (int i = 0; i < 8; ++i) {
                int pt = ty * 8 + i;
                if (pt < npts) {
                    float thr = gmin8[i] + sMar[pt];
                    int n = p0 + pt;
                    #pragma unroll
                    for (int j = 0; j < 4; ++j) {
                        float dd = __int_as_float(m[i * 4 + j]);
                        if (dd <= thr) {
                            u32 s = atomicAdd(&g_ccnt[n], 1u);
                            if (s < CMAXC) {
                                g_cand[(size_t)n * CMAXC + s] = (u16)(t * 128 + tx * 4 + j);
                                g_cdda[(size_t)n * CMAXC + s] = dd;
                            }
                        }
                    }
                }
            }
        }
        if (t < 7) cp_wait0();
        __syncthreads();
    }
    if (tx == 0) {
        #pragma unroll
        for (int i = 0; i < 8; ++i) {
            int pt = ty * 8 + i;
            if (pt < npts) g_minq[p0 + pt] = gmin8[i];
        }
    }
}

// ---------------------------------------------------------------------------
// Fused exact re-rank + gather (unchanged from R11; profiled this round).
// ---------------------------------------------------------------------------
#define XSTR 260
__global__ void __launch_bounds__(256)
exact_gather_kernel(const float* __restrict__ z, const float* __restrict__ cb,
                    float* __restrict__ out) {
    extern __shared__ float sh[];               // xS[32][260] | tile[32][260]
    float (*xS)[XSTR]   = (float(*)[XSTR])sh;
    float (*tile)[XSTR] = (float(*)[XSTR])(sh + 32 * XSTR);
    __shared__ u32 wl[2048];
    __shared__ u64 best[32];
    __shared__ int sidx[32];
    __shared__ u32 wcnt;
    __shared__ int ovf;

    const int tid = threadIdx.x;
    const int p0 = blockIdx.x * 32, b = p0 >> 10, hw0 = p0 & 1023;
    const float* zb = z + (size_t)b * DHW + hw0;

    if (tid == 0) { wcnt = 0; ovf = 0; }
    if (tid < 32) best[tid] = ~0ull;
    for (int lin = tid; lin < 2048; lin += 256) {
        int d = lin >> 3, q4 = (lin & 7) << 2;
        float4 v = *(const float4*)(zb + (size_t)d * HWSZ + q4);
        xS[q4 + 0][d] = v.x;
        xS[q4 + 1][d] = v.y;
        xS[q4 + 2][d] = v.z;
        xS[q4 + 3][d] = v.w;
    }
    __syncthreads();

    {
        int p = tid & 31, s = tid >> 5;
        int n = p0 + p;
        u32 cnt = g_ccnt[n];
        if (cnt > CMAXC) {
            if (s == 0) ovf = 1;
        } else {
            float thr = g_minq[n] + g_mar[n];
            for (u32 c = s; c < cnt; c += 8) {
                if (g_cdda[(size_t)n * CMAXC + c] <= thr) {
                    u32 id = atomicAdd(&wcnt, 1u);
                    wl[id] = ((u32)p << 10) | (u32)g_cand[(size_t)n * CMAXC + c];
                }
            }
        }
    }
    __syncthreads();

    {
        u32 W = wcnt;
        for (u32 i = tid; i < W; i += 256) {
            int p = wl[i] >> 10, k = wl[i] & 1023;
            const float4* crow = (const float4*)(cb + (size_t)k * DDIM);
            float mm = 0.0f;
            #pragma unroll 8
            for (int d4 = 0; d4 < DDIM / 4; ++d4) {
                float4 cv = crow[d4];
                const float* xp = &xS[p][d4 * 4];
                mm = __fmaf_rn(xp[0], cv.x, mm);
                mm = __fmaf_rn(xp[1], cv.y, mm);
                mm = __fmaf_rn(xp[2], cv.z, mm);
                mm = __fmaf_rn(xp[3], cv.w, mm);
            }
            float t1 = __fadd_rn(g_xx[p0 + p], g_cs4[k].x);
            float dd = __fadd_rn(t1, -(2.0f * mm));
            u64 pack = ((u64)(u32)__float_as_int(dd) << 32) | (u32)k;
            atomicMin(&best[p], pack);
        }
    }
    if (ovf) {
        int p = tid & 31, s = tid >> 5;
        int n = p0 + p;
        if (g_ccnt[n] > CMAXC) {
            for (int k = s; k < KCODES; k += 8) {
                const float4* crow = (const float4*)(cb + (size_t)k * DDIM);
                float mm = 0.0f;
                #pragma unroll 8
                for (int d4 = 0; d4 < DDIM / 4; ++d4) {
                    float4 cv = crow[d4];
                    const float* xp = &xS[p][d4 * 4];
                    mm = __fmaf_rn(xp[0], cv.x, mm);
                    mm = __fmaf_rn(xp[1], cv.y, mm);
                    mm = __fmaf_rn(xp[2], cv.z, mm);
                    mm = __fmaf_rn(xp[3], cv.w, mm);
                }
                float t1 = __fadd_rn(g_xx[n], g_cs4[k].x);
                float dd = __fadd_rn(t1, -(2.0f * mm));
                u64 pack = ((u64)(u32)__float_as_int(dd) << 32) | (u32)k;
                atomicMin(&best[p], pack);
            }
        }
    }
    __syncthreads();
    if (tid < 32) sidx[tid] = (int)(best[tid] & 1023u);
    __syncthreads();

    #pragma unroll
    for (int r = 0; r < 8; ++r) {
        int lin = tid + r * 256;
        int p = lin >> 6;
        int d4 = (lin & 63) << 2;
        float4 v = *reinterpret_cast<const float4*>(cb + (size_t)sidx[p] * DDIM + d4);
        tile[p][d4 + 0] = v.x;
        tile[p][d4 + 1] = v.y;
        tile[p][d4 + 2] = v.z;
        tile[p][d4 + 3] = v.w;
    }
    __syncthreads();

    float* o1 = out + (size_t)b * DHW + hw0;
    const int q4 = (tid & 7) << 2;
    const int dch = tid >> 3;
    #pragma unroll
    for (int r = 0; r < 8; ++r) {
        int d = r * 32 + dch;
        size_t off = (size_t)d * HWSZ + q4;
        float4 xv = make_float4(xS[q4][d], xS[q4 + 1][d], xS[q4 + 2][d], xS[q4 + 3][d]);
        float4 qv = make_float4(tile[q4][d], tile[q4 + 1][d], tile[q4 + 2][d], tile[q4 + 3][d]);
        float4 ov;
        ov.x = __fadd_rn(xv.x, __fadd_rn(qv.x, -xv.x));
        ov.y = __fadd_rn(xv.y, __fadd_rn(qv.y, -xv.y));
        ov.z = __fadd_rn(xv.z, __fadd_rn(qv.z, -xv.z));
        ov.w = __fadd_rn(xv.w, __fadd_rn(qv.w, -xv.w));
        *(float4*)(o1 + off)            = ov;
        *(float4*)(o1 + off + HALF_OUT) = qv;
    }
}

// ---------------------------------------------------------------------------
extern "C" void kernel_launch(void* const* d_in, const int* in_sizes, int n_in,
                              void* d_out, int out_size) {
    const float* z  = (const float*)d_in[0];   // z_e_x  [32,256,32,32]
    const float* cb = (const float*)d_in[1];   // codebook [1024,256]
    float* out = (float*)d_out;                // [2, 32,256,32,32]

    static int inited = 0;
    if (!inited) {
        cudaFuncSetAttribute(pass1_kernel,
                             cudaFuncAttributeMaxDynamicSharedMemorySize, 106496);
        cudaFuncSetAttribute(exact_gather_kernel,
                             cudaFuncAttributeMaxDynamicSharedMemorySize,
                             2 * 32 * XSTR * 4);
        inited = 1;
    }

    code_prep<<<128, 256>>>(cb);
    nop_a<<<1, 1>>>();
    pass1_kernel<<<GRID1, 512, 106496>>>(z);
    exact_gather_kernel<<<NPTS / 32, 256, 2 * 32 * XSTR * 4>>>(z, cb, out);
}

// round 13
// speedup vs baseline: 1.0986x; 1.0986x over previous
#include <cuda_runtime.h>
#include <cstdint>

#define NPTS     32768
#define KCODES   1024
#define DDIM     256
#define HWSZ     1024
#define DHW      (DDIM*HWSZ)
#define HALF_OUT 8388608
#define CMAXC    64
#define PPC      111          // points per pass1 CTA (296 x 111 >= 32768)
#define GRID1    296          // 2 CTAs/SM -> exactly one wave

typedef unsigned int u32;
typedef unsigned short u16;
typedef unsigned long long u64;

// Scratch (static __device__ — no allocations)
__device__ u32    g_c8T[KCODES * 64];   // [8 tile][64 word][128 code] packed int8
__device__ float4 g_cs4[KCODES];        // (cc exact-chain, sc=max|c|, rc=||Δc||, 0)
__device__ float  g_xx[NPTS];
__device__ float  g_mar[NPTS];
__device__ float  g_minq[NPTS];
__device__ u16    g_cand[NPTS * CMAXC];
__device__ float  g_cdda[NPTS * CMAXC];
__device__ u32    g_ccnt[NPTS];
__device__ int    g_idx[NPTS];

__device__ __forceinline__ u32 smem_u32(const void* p) {
    return (u32)__cvta_generic_to_shared(p);
}
__device__ __forceinline__ void cp_async16(u32 dst, const void* src) {
    asm volatile("cp.async.cg.shared.global [%0], [%1], 16;" :: "r"(dst), "l"(src));
}
__device__ __forceinline__ void cp_commit() { asm volatile("cp.async.commit_group;"); }
__device__ __forceinline__ void cp_wait0()  { asm volatile("cp.async.wait_group 0;" ::: "memory"); }

// ncu capture slot #4: code_prep(1), nop_a(2), pass1(3), exact_rank(4).
__global__ void nop_a() {}

// ---------------------------------------------------------------------------
// code_prep: one WARP per code (unchanged, 6.2us).
// ---------------------------------------------------------------------------
__global__ void code_prep(const float* __restrict__ cb) {
    const int tid = threadIdx.x, lane = tid & 31, wid = tid >> 5;
    const int k = blockIdx.x * 8 + wid;
    const float* row = cb + (size_t)k * DDIM;

    float4 va = *(const float4*)(row + lane * 8);
    float4 vb = *(const float4*)(row + lane * 8 + 4);
    float mx = fmaxf(fmaxf(fmaxf(fabsf(va.x), fabsf(va.y)), fmaxf(fabsf(va.z), fabsf(va.w))),
                     fmaxf(fmaxf(fabsf(vb.x), fabsf(vb.y)), fmaxf(fabsf(vb.z), fabsf(vb.w))));
    #pragma unroll
    for (int o = 16; o; o >>= 1) mx = fmaxf(mx, __shfl_xor_sync(0xFFFFFFFFu, mx, o));

    float mxx = fmaxf(mx, 1e-30f);
    float s127 = 127.0f / mxx;
    float cinv = mxx / 127.0f;

    float rsum = 0.0f;
    u32 base = (u32)(k >> 7) * 8192u + (u32)(k & 127);
    float vv[8] = {va.x, va.y, va.z, va.w, vb.x, vb.y, vb.z, vb.w};
    #pragma unroll
    for (int h = 0; h < 2; ++h) {
        u32 pk = 0;
        #pragma unroll
        for (int e = 0; e < 4; ++e) {
            float ve = vv[h * 4 + e];
            int q = __float2int_rn(ve * s127);
            q = max(-127, min(127, q));
            float diff = fmaf(-(float)q, cinv, ve);
            rsum += diff * diff;
            pk |= ((u32)(q & 0xFF)) << (8 * e);
        }
        g_c8T[base + (u32)(lane * 2 + h) * 128u] = pk;
    }
    #pragma unroll
    for (int o = 16; o; o >>= 1) rsum += __shfl_xor_sync(0xFFFFFFFFu, rsum, o);

    if (lane == 0) {
        float s = 0.0f;
        for (int d0 = 0; d0 < DDIM; d0 += 16) {
            float4 w0 = *(const float4*)(row + d0);
            float4 w1 = *(const float4*)(row + d0 + 4);
            float4 w2 = *(const float4*)(row + d0 + 8);
            float4 w3 = *(const float4*)(row + d0 + 12);
            float v[16] = {w0.x, w0.y, w0.z, w0.w, w1.x, w1.y, w1.z, w1.w,
                           w2.x, w2.y, w2.z, w2.w, w3.x, w3.y, w3.z, w3.w};
            #pragma unroll
            for (int e = 0; e < 16; ++e)
                s = __fadd_rn(s, __fmul_rn(v[e], v[e]));
        }
        g_cs4[k] = make_float4(s, mx, sqrtf(rsum) * 1.02f + 1e-7f, 0.0f);
    }
}

// ---------------------------------------------------------------------------
// Pass 1: 512 threads, 8pts x 4codes, 2 CTAs/SM (R11 mainloop; sCS epilogue).
// ---------------------------------------------------------------------------
__global__ void __launch_bounds__(512, 2)
pass1_kernel(const float* __restrict__ z) {
    extern __shared__ u32 sdyn[];   // As[8192] | Bs0[8192] | Bs1[8192] | sCS[2048]
    u32* As = sdyn;
    u32* Bsb[2] = { sdyn + 8192, sdyn + 16384 };
    float2* sCS = (float2*)(sdyn + 24576);      // (cc, sc) per code, 8KB
    __shared__ float sMar[128], sXX[128], sSX[128], sRX[128];
    __shared__ float sred[2][16];

    const int tid = threadIdx.x;
    const int tx = tid & 31;          // lane -> 4 codes at tx*4
    const int ty = tid >> 5;          // warp -> 8 points at ty*8
    const int p0 = blockIdx.x * PPC;
    const int npts = min(PPC, NPTS - p0);

    // Prefetch B tile 0 (overlaps entire prologue)
    {
        u32 db = smem_u32(Bsb[0]);
        #pragma unroll
        for (int r = 0; r < 4; ++r)
            cp_async16(db + (u32)(r * 512 + tid) * 16u, g_c8T + (r * 512 + tid) * 4);
        cp_commit();
    }

    // Preload (cc, sc) into smem + block maxes (cc, rc)
    {
        float mcc = 0.0f, mrc = 0.0f;
        #pragma unroll
        for (int l = 0; l < 2; ++l) {
            int k = tid + l * 512;
            float4 cs = g_cs4[k];
            sCS[k] = make_float2(cs.x, cs.y);
            mcc = fmaxf(mcc, cs.x);
            mrc = fmaxf(mrc, cs.z);
        }
        #pragma unroll
        for (int o = 16; o; o >>= 1) {
            mcc = fmaxf(mcc, __shfl_xor_sync(0xFFFFFFFFu, mcc, o));
            mrc = fmaxf(mrc, __shfl_xor_sync(0xFFFFFFFFu, mrc, o));
        }
        if (tx == 0) { sred[0][ty] = mcc; sred[1][ty] = mrc; }
    }

    // x-prep: threads 0-127 pinned xx chains; 128-255 pack + residual.
    if (tid < 128) {
        const int p = tid, n = p0 + p;
        if (p < npts) {
            const int bb = n >> 10, hw = n & 1023;
            const float* bp = z + (size_t)bb * DHW + hw;
            g_ccnt[n] = 0;
            float s = 0.0f;
            for (int d0 = 0; d0 < DDIM; d0 += 16) {
                float v[16];
                #pragma unroll
                for (int e = 0; e < 16; ++e) v[e] = bp[(size_t)(d0 + e) * HWSZ];
                #pragma unroll
                for (int e = 0; e < 16; ++e)
                    s = __fadd_rn(s, __fmul_rn(v[e], v[e]));
            }
            g_xx[n] = s;
            sXX[p] = s;
        } else {
            sXX[p] = 3.0e38f;
        }
    } else if (tid < 256) {
        const int p = tid - 128, n = p0 + p;
        if (p < npts) {
            const int bb = n >> 10, hw = n & 1023;
            const float* bp = z + (size_t)bb * DHW + hw;
            float mx = 0.0f;
            for (int d0 = 0; d0 < DDIM; d0 += 16) {
                float v[16];
                #pragma unroll
                for (int e = 0; e < 16; ++e) v[e] = bp[(size_t)(d0 + e) * HWSZ];
                #pragma unroll
                for (int e = 0; e < 16; ++e) mx = fmaxf(mx, fabsf(v[e]));
            }
            float mxx = fmaxf(mx, 1e-30f);
            float s127 = 127.0f / mxx;
            float xinv = mxx / 127.0f;
            float rsum = 0.0f;
            #pragma unroll 4
            for (int w = 0; w < 64; ++w) {
                u32 pk = 0;
                #pragma unroll
                for (int e = 0; e < 4; ++e) {
                    float xe = bp[(size_t)(w * 4 + e) * HWSZ];   // L2 hit
                    int q = __float2int_rn(xe * s127);
                    q = max(-127, min(127, q));
                    float diff = fmaf(-(float)q, xinv, xe);
                    rsum += diff * diff;
                    pk |= ((u32)(q & 0xFF)) << (8 * e);
                }
                As[w * 128 + p] = pk;
            }
            sSX[p] = mx * (1.0f / 16129.0f);
            sRX[p] = sqrtf(rsum) * 1.02f + 1e-7f;
        } else {
            #pragma unroll 8
            for (int w = 0; w < 64; ++w) As[w * 128 + p] = 0u;
            sSX[p] = 0.0f;
            sRX[p] = 0.0f;
        }
    }
    __syncthreads();

    float MCC = 0.0f, MRC = 0.0f;
    #pragma unroll
    for (int i = 0; i < 16; ++i) {
        MCC = fmaxf(MCC, sred[0][i]);
        MRC = fmaxf(MRC, sred[1][i]);
    }
    const float Smax = sqrtf(MCC);

    if (tid < 128) {
        const int p = tid;
        if (p < npts) {
            float rx = sRX[p], s = sXX[p];
            float errdot = rx * Smax + (sqrtf(s) + rx) * MRC;
            float marg = 2.5f * errdot + 2e-4f;
            sMar[p] = marg;
            g_mar[p0 + p] = marg;
        } else {
            sMar[p] = 0.0f;
        }
    }
    cp_wait0();
    __syncthreads();

    float gmin8[8];
    #pragma unroll
    for (int i = 0; i < 8; ++i) gmin8[i] = 3.0e38f;

    for (int t = 0; t < 8; ++t) {
        if (t < 7) {
            u32 db = smem_u32(Bsb[(t + 1) & 1]);
            const u32* src = g_c8T + (t + 1) * 8192;
            #pragma unroll
            for (int r = 0; r < 4; ++r)
                cp_async16(db + (u32)(r * 512 + tid) * 16u, src + (r * 512 + tid) * 4);
            cp_commit();
        }
        const uint4* Bt4 = (const uint4*)Bsb[t & 1];
        const uint4* At4 = (const uint4*)As;

        int m[32];
        #pragma unroll
        for (int i = 0; i < 32; ++i) m[i] = 0;

        #pragma unroll 4
        for (int w = 0; w < 64; ++w) {
            uint4 A0 = At4[w * 32 + ty * 2];       // broadcast within warp
            uint4 A1 = At4[w * 32 + ty * 2 + 1];
            uint4 B  = Bt4[w * 32 + tx];
            int a[8] = {(int)A0.x, (int)A0.y, (int)A0.z, (int)A0.w,
                        (int)A1.x, (int)A1.y, (int)A1.z, (int)A1.w};
            int bb[4] = {(int)B.x, (int)B.y, (int)B.z, (int)B.w};
            #pragma unroll
            for (int i = 0; i < 8; ++i)
                #pragma unroll
                for (int j = 0; j < 4; ++j)
                    m[i * 4 + j] = __dp4a(a[i], bb[j], m[i * 4 + j]);
        }

        // Epilogue: distances (cc/sc from smem) + full-warp shuffle min
        {
            float xx8[8], sx8[8], lmin8[8];
            #pragma unroll
            for (int i = 0; i < 8; ++i) {
                xx8[i] = sXX[ty * 8 + i];
                sx8[i] = sSX[ty * 8 + i];
                lmin8[i] = 3.0e38f;
            }
            #pragma unroll
            for (int j = 0; j < 4; ++j) {
                float2 cj = sCS[t * 128 + tx * 4 + j];
                #pragma unroll
                for (int i = 0; i < 8; ++i) {
                    float dd = fmaf(-2.0f * sx8[i] * cj.y,
                                    (float)m[i * 4 + j], xx8[i] + cj.x);
                    m[i * 4 + j] = __float_as_int(dd);
                    lmin8[i] = fminf(lmin8[i], dd);
                }
            }
            #pragma unroll
            for (int i = 0; i < 8; ++i) {
                float v = lmin8[i];
                #pragma unroll
                for (int o = 1; o < 32; o <<= 1)
                    v = fminf(v, __shfl_xor_sync(0xFFFFFFFFu, v, o));
                gmin8[i] = fminf(gmin8[i], v);
            }
            #pragma unroll
            for (int i = 0; i < 8; ++i) {
                int pt = ty * 8 + i;
                if (pt < npts) {
                    float thr = gmin8[i] + sMar[pt];
                    int n = p0 + pt;
                    #pragma unroll
                    for (int j = 0; j < 4; ++j) {
                        float dd = __int_as_float(m[i * 4 + j]);
                        if (dd <= thr) {
                            u32 s = atomicAdd(&g_ccnt[n], 1u);
                            if (s < CMAXC) {
                                g_cand[(size_t)n * CMAXC + s] = (u16)(t * 128 + tx * 4 + j);
                                g_cdda[(size_t)n * CMAXC + s] = dd;
                            }
                        }
                    }
                }
            }
        }
        if (t < 7) cp_wait0();
        __syncthreads();
    }
    if (tx == 0) {
        #pragma unroll
        for (int i = 0; i < 8; ++i) {
            int pt = ty * 8 + i;
            if (pt < npts) g_minq[p0 + pt] = gmin8[i];
        }
    }
}

// ---------------------------------------------------------------------------
// exact_rank: 32 pts/block, ~42KB smem -> ~5 CTAs/SM so phase latencies
// overlap across blocks. Stage x (L2-resident), filter final window into a
// worklist, run R1-proven bitwise chains, atomicMin lexicographic (dd, k),
// write g_idx. No output streaming here.
// ---------------------------------------------------------------------------
#define XSTR 260
__global__ void __launch_bounds__(256)
exact_rank_kernel(const float* __restrict__ z, const float* __restrict__ cb) {
    __shared__ float xS[32][XSTR];
    __shared__ u32 wl[2048];
    __shared__ u64 best[32];
    __shared__ u32 wcnt;
    __shared__ int ovf;

    const int tid = threadIdx.x;
    const int p0 = blockIdx.x * 32, b = p0 >> 10, hw0 = p0 & 1023;
    const float* zb = z + (size_t)b * DHW + hw0;

    if (tid == 0) { wcnt = 0; ovf = 0; }
    if (tid < 32) best[tid] = ~0ull;
    for (int lin = tid; lin < 2048; lin += 256) {
        int d = lin >> 3, q4 = (lin & 7) << 2;
        float4 v = *(const float4*)(zb + (size_t)d * HWSZ + q4);
        xS[q4 + 0][d] = v.x;
        xS[q4 + 1][d] = v.y;
        xS[q4 + 2][d] = v.z;
        xS[q4 + 3][d] = v.w;
    }
    __syncthreads();

    // Filter survivors of the FINAL window into worklist
    {
        int p = tid & 31, s = tid >> 5;
        int n = p0 + p;
        u32 cnt = g_ccnt[n];
        if (cnt > CMAXC) {
            if (s == 0) ovf = 1;
        } else {
            float thr = g_minq[n] + g_mar[n];
            for (u32 c = s; c < cnt; c += 8) {
                if (g_cdda[(size_t)n * CMAXC + c] <= thr) {
                    u32 id = atomicAdd(&wcnt, 1u);
                    wl[id] = ((u32)p << 10) | (u32)g_cand[(size_t)n * CMAXC + c];
                }
            }
        }
    }
    __syncthreads();

    // Exact chains (R1-proven bitwise form), round-robin over worklist
    {
        u32 W = wcnt;
        for (u32 i = tid; i < W; i += 256) {
            int p = wl[i] >> 10, k = wl[i] & 1023;
            const float4* crow = (const float4*)(cb + (size_t)k * DDIM);
            float mm = 0.0f;
            #pragma unroll 8
            for (int d4 = 0; d4 < DDIM / 4; ++d4) {
                float4 cv = crow[d4];
                const float* xp = &xS[p][d4 * 4];
                mm = __fmaf_rn(xp[0], cv.x, mm);
                mm = __fmaf_rn(xp[1], cv.y, mm);
                mm = __fmaf_rn(xp[2], cv.z, mm);
                mm = __fmaf_rn(xp[3], cv.w, mm);
            }
            float t1 = __fadd_rn(g_xx[p0 + p], g_cs4[k].x);
            float dd = __fadd_rn(t1, -(2.0f * mm));
            u64 pack = ((u64)(u32)__float_as_int(dd) << 32) | (u32)k;
            atomicMin(&best[p], pack);
        }
    }
    if (ovf) {   // essentially-never fallback: full exact scan
        int p = tid & 31, s = tid >> 5;
        int n = p0 + p;
        if (g_ccnt[n] > CMAXC) {
            for (int k = s; k < KCODES; k += 8) {
                const float4* crow = (const float4*)(cb + (size_t)k * DDIM);
                float mm = 0.0f;
                #pragma unroll 8
                for (int d4 = 0; d4 < DDIM / 4; ++d4) {
                    float4 cv = crow[d4];
                    const float* xp = &xS[p][d4 * 4];
                    mm = __fmaf_rn(xp[0], cv.x, mm);
                    mm = __fmaf_rn(xp[1], cv.y, mm);
                    mm = __fmaf_rn(xp[2], cv.z, mm);
                    mm = __fmaf_rn(xp[3], cv.w, mm);
                }
                float t1 = __fadd_rn(g_xx[n], g_cs4[k].x);
                float dd = __fadd_rn(t1, -(2.0f * mm));
                u64 pack = ((u64)(u32)__float_as_int(dd) << 32) | (u32)k;
                atomicMin(&best[p], pack);
            }
        }
    }
    __syncthreads();
    if (tid < 32) g_idx[p0 + tid] = (int)(best[tid] & 1023u);
}

// ---------------------------------------------------------------------------
// Gather + straight-through outputs (R2/R7-proven form, ~19.5us).
// ---------------------------------------------------------------------------
#define GPTS 32
__global__ void __launch_bounds__(256)
gather_kernel(const float* __restrict__ z, const float* __restrict__ cb,
              float* __restrict__ out) {
    __shared__ float tile[GPTS][DDIM + 1];
    __shared__ int sidx[GPTS];

    const int tid = threadIdx.x;
    const int p0 = blockIdx.x * GPTS;
    const int b = p0 >> 10;
    const int hw0 = p0 & 1023;

    if (tid < GPTS) sidx[tid] = g_idx[p0 + tid];
    __syncthreads();

    #pragma unroll
    for (int r = 0; r < 8; ++r) {
        int lin = tid + r * 256;
        int p = lin >> 6;
        int d4 = (lin & 63) << 2;
        float4 v = *reinterpret_cast<const float4*>(cb + (size_t)sidx[p] * DDIM + d4);
        tile[p][d4 + 0] = v.x;
        tile[p][d4 + 1] = v.y;
        tile[p][d4 + 2] = v.z;
        tile[p][d4 + 3] = v.w;
    }
    __syncthreads();

    const float* zb = z + (size_t)b * DHW + hw0;
    float* o1 = out + (size_t)b * DHW + hw0;
    const int p = tid & 31;
    const int dchunk = tid >> 5;

    #pragma unroll
    for (int dd = 0; dd < DDIM; dd += 8) {
        int d = dd + dchunk;
        size_t off = (size_t)d * HWSZ + p;
        float x = zb[off];
        float q = tile[p][d];
        float t = __fadd_rn(q, -x);
        o1[off]            = __fadd_rn(x, t);
        o1[off + HALF_OUT] = q;
    }
}

// ---------------------------------------------------------------------------
extern "C" void kernel_launch(void* const* d_in, const int* in_sizes, int n_in,
                              void* d_out, int out_size) {
    const float* z  = (const float*)d_in[0];   // z_e_x  [32,256,32,32]
    const float* cb = (const float*)d_in[1];   // codebook [1024,256]
    float* out = (float*)d_out;                // [2, 32,256,32,32]

    static int inited = 0;
    if (!inited) {
        cudaFuncSetAttribute(pass1_kernel,
                             cudaFuncAttributeMaxDynamicSharedMemorySize, 106496);
        inited = 1;
    }

    code_prep<<<128, 256>>>(cb);
    nop_a<<<1, 1>>>();
    pass1_kernel<<<GRID1, 512, 106496>>>(z);
    exact_rank_kernel<<<NPTS / 32, 256>>>(z, cb);       // ncu slot #4
    gather_kernel<<<NPTS / GPTS, 256>>>(z, cb, out);
}